// round 1
// baseline (speedup 1.0000x reference)
#include <cuda_runtime.h>
#include <cstdint>
#include <math.h>

#define NHEADS   16
#define NKV      4
#define HDIM     128
#define HIDDEN   2048
#define MAXSEQ   1024
#define EPSV     1e-6f
#define QSCALE   0.088388347648318447f   /* 1/sqrt(128) */

// ---------------- scratch (static device allocations; no runtime alloc) ----
__device__ float g_part[24 * 8 * 32 * 128];   // K-split GEMM partials (3 MB)
__device__ float g_q[32 * NHEADS * HDIM];     // normed+roped+scaled q
__device__ float g_k[32 * NKV * HDIM];        // normed+roped new k (row POS)
__device__ float g_v[32 * NKV * HDIM];        // new v (row POS)
__device__ float g_attn[32 * HIDDEN];         // attention output, pre-Wo

// ---------------------------------------------------------------------------
// Shared GEMM tile: 32 batches x 128 features x 256-K slice, fp32.
// Block = 256 threads; per-thread 2x8 register tile. Writes [32][128] partial.
// ---------------------------------------------------------------------------
__device__ __forceinline__ void gemm_block(const float* __restrict__ X,
                                           const float* __restrict__ Wt,
                                           float* __restrict__ outp,
                                           int kstart)
{
    __shared__ float w_s[32][132];   // [k][f], pad 132 keeps 16B alignment
    __shared__ float x_s[32][34];    // [k][b], pad 34 keeps 8B alignment

    const int tid = threadIdx.x;
    const int tx  = tid & 15;        // feature group: f = tx*8 .. tx*8+7
    const int ty  = tid >> 4;        // batch pair:    b = ty*2, ty*2+1

    float acc[2][8];
#pragma unroll
    for (int i = 0; i < 2; i++)
#pragma unroll
        for (int j = 0; j < 8; j++) acc[i][j] = 0.f;

    const int kq = (tid & 7) * 4;    // k offset for loaders
    const int fb = tid >> 3;         // 0..31

    for (int kc = 0; kc < 256; kc += 32) {
        const int kb = kstart + kc;
        // load W chunk (128 f x 32 k), transposed into w_s[k][f]
#pragma unroll
        for (int r = 0; r < 4; r++) {
            const int f = fb + r * 32;
            float4 v = *(const float4*)(Wt + (size_t)f * HIDDEN + kb + kq);
            w_s[kq + 0][f] = v.x;
            w_s[kq + 1][f] = v.y;
            w_s[kq + 2][f] = v.z;
            w_s[kq + 3][f] = v.w;
        }
        // load X chunk (32 b x 32 k), transposed into x_s[k][b]
        {
            const int b = fb;
            float4 v = *(const float4*)(X + (size_t)b * HIDDEN + kb + kq);
            x_s[kq + 0][b] = v.x;
            x_s[kq + 1][b] = v.y;
            x_s[kq + 2][b] = v.z;
            x_s[kq + 3][b] = v.w;
        }
        __syncthreads();
#pragma unroll
        for (int k = 0; k < 32; k++) {
            const float xs0 = x_s[k][ty * 2 + 0];
            const float xs1 = x_s[k][ty * 2 + 1];
            const float* wp = &w_s[k][tx * 8];
#pragma unroll
            for (int j = 0; j < 8; j++) {
                const float wv = wp[j];
                acc[0][j] = fmaf(xs0, wv, acc[0][j]);
                acc[1][j] = fmaf(xs1, wv, acc[1][j]);
            }
        }
        __syncthreads();
    }
#pragma unroll
    for (int j = 0; j < 8; j++) {
        outp[(ty * 2 + 0) * 128 + tx * 8 + j] = acc[0][j];
        outp[(ty * 2 + 1) * 128 + tx * 8 + j] = acc[1][j];
    }
}

// grid (24 tiles, 8 k-slices): tiles 0..15 = wq rows, 16..19 = wk, 20..23 = wv
__global__ __launch_bounds__(256) void gemm_qkv(const float* __restrict__ x,
                                                const float* __restrict__ wq,
                                                const float* __restrict__ wk,
                                                const float* __restrict__ wv)
{
    const int tile = blockIdx.x, slice = blockIdx.y;
    const float* Wt;
    if (tile < 16)      Wt = wq + (size_t)tile * 128 * HIDDEN;
    else if (tile < 20) Wt = wk + (size_t)(tile - 16) * 128 * HIDDEN;
    else                Wt = wv + (size_t)(tile - 20) * 128 * HIDDEN;
    gemm_block(x, Wt, g_part + (size_t)(tile * 8 + slice) * 4096, slice * 256);
}

// grid (16 tiles, 8 k-slices): output projection partials
__global__ __launch_bounds__(256) void gemm_o(const float* __restrict__ wo)
{
    const int tile = blockIdx.x, slice = blockIdx.y;
    gemm_block(g_attn, wo + (size_t)tile * 128 * HIDDEN,
               g_part + (size_t)(tile * 8 + slice) * 4096, slice * 256);
}

// ---------------------------------------------------------------------------
// Reduce K-split partials for QKV, then RMSnorm + RoPE (q & k heads).
// grid (24 heads, 32 batches) x 128 threads. Head tile: 0..15 q, 16..19 k,
// 20..23 v (v: plain reduce).
// ---------------------------------------------------------------------------
__global__ __launch_bounds__(128) void reduce_norm_rope(
    const float* __restrict__ position,
    const float* __restrict__ qnw, const float* __restrict__ knw)
{
    const int head = blockIdx.x, b = blockIdx.y, d = threadIdx.x;
    const size_t base = (size_t)head * 32768 + (size_t)b * 128 + d;
    float v = 0.f;
#pragma unroll
    for (int s = 0; s < 8; s++) v += g_part[base + (size_t)s * 4096];

    if (head >= 20) {                       // v head: no norm / rope
        g_v[(b * NKV + head - 20) * HDIM + d] = v;
        return;
    }

    __shared__ float red[4];
    __shared__ float sv[128];

    float sq = v * v;
#pragma unroll
    for (int off = 16; off; off >>= 1)
        sq += __shfl_xor_sync(0xffffffffu, sq, off);
    if ((d & 31) == 0) red[d >> 5] = sq;
    __syncthreads();
    const float ssq  = red[0] + red[1] + red[2] + red[3];
    const float norm = rsqrtf(ssq * (1.f / 128.f) + EPSV);
    const float nv   = v * norm * ((head < 16) ? qnw[d] : knw[d]);
    sv[d] = nv;
    __syncthreads();

    const float pos = position[0];
    const int   j   = d & 63;
    // inv_freq = THETA^(-j/64), THETA=1e6; log2(1e6)=19.93156856932417
    const float fr  = pos * exp2f((float)j * (-19.93156856932417f / 64.f));
    float c, s;
    sincosf(fr, &s, &c);
    const float other = (d < 64) ? sv[d + 64] : sv[d - 64];
    const float out   = (d < 64) ? (nv * c - other * s)
                                 : (nv * c + other * s);
    if (head < 16) g_q[(b * NHEADS + head) * HDIM + d] = out * QSCALE;
    else           g_k[(b * NKV + head - 16) * HDIM + d] = out;
}

// ---------------------------------------------------------------------------
// Attention: one block per (kv-head, batch). 4 grouped q-heads share the
// K/V cache read (cache read exactly once). Two-pass softmax with scores in
// smem; s==pos rows come from the fresh k/v.
// ---------------------------------------------------------------------------
__global__ __launch_bounds__(256) void attn_kernel(
    const float* __restrict__ k_cache, const float* __restrict__ v_cache,
    const float* __restrict__ position)
{
    const int kv = blockIdx.x, b = blockIdx.y;
    const int tid = threadIdx.x;
    const int lane = tid & 31, w = tid >> 5;
    const int pos = (int)position[0];
    const int S = pos + 1;                  // masked tail contributes exact 0

    __shared__ float q_s[4][HDIM];
    __shared__ float sc[4][MAXSEQ];
    __shared__ float wred[8][4];
    __shared__ float gm[4];
    __shared__ float ginv[4];
    __shared__ float wout[8][4][HDIM];

    for (int i = tid; i < 4 * HDIM; i += 256) {
        const int h = i >> 7, d = i & 127;
        q_s[h][d] = g_q[(b * NHEADS + kv * 4 + h) * HDIM + d]; // pre-scaled
    }
    __syncthreads();

    float qr[4][4];
#pragma unroll
    for (int h = 0; h < 4; h++)
#pragma unroll
        for (int j = 0; j < 4; j++) qr[h][j] = q_s[h][lane * 4 + j];

    const float* kbase = k_cache + (size_t)(b * NKV + kv) * MAXSEQ * HDIM;
    const float* knew  = g_k + (b * NKV + kv) * HDIM;

    float wmax[4] = {-1e30f, -1e30f, -1e30f, -1e30f};

    // ---- phase 1: scores (warp w covers s in [w*4, w*4+4) per 32-stride) ---
    for (int s0 = w * 4; s0 < S; s0 += 32) {
        float4 r[4];
#pragma unroll
        for (int u = 0; u < 4; u++) {
            const int s = s0 + u;
            if (s < S) {
                const float* row = (s == pos) ? knew
                                              : (kbase + (size_t)s * HDIM);
                r[u] = *(const float4*)(row + lane * 4);
            }
        }
#pragma unroll
        for (int u = 0; u < 4; u++) {
            const int s = s0 + u;
            if (s < S) {
                float d0 = fmaf(r[u].x, qr[0][0], fmaf(r[u].y, qr[0][1],
                           fmaf(r[u].z, qr[0][2], r[u].w * qr[0][3])));
                float d1 = fmaf(r[u].x, qr[1][0], fmaf(r[u].y, qr[1][1],
                           fmaf(r[u].z, qr[1][2], r[u].w * qr[1][3])));
                float d2 = fmaf(r[u].x, qr[2][0], fmaf(r[u].y, qr[2][1],
                           fmaf(r[u].z, qr[2][2], r[u].w * qr[2][3])));
                float d3 = fmaf(r[u].x, qr[3][0], fmaf(r[u].y, qr[3][1],
                           fmaf(r[u].z, qr[3][2], r[u].w * qr[3][3])));
#pragma unroll
                for (int off = 16; off; off >>= 1) {
                    d0 += __shfl_xor_sync(0xffffffffu, d0, off);
                    d1 += __shfl_xor_sync(0xffffffffu, d1, off);
                    d2 += __shfl_xor_sync(0xffffffffu, d2, off);
                    d3 += __shfl_xor_sync(0xffffffffu, d3, off);
                }
                wmax[0] = fmaxf(wmax[0], d0);
                wmax[1] = fmaxf(wmax[1], d1);
                wmax[2] = fmaxf(wmax[2], d2);
                wmax[3] = fmaxf(wmax[3], d3);
                if (lane == 0) {
                    sc[0][s] = d0; sc[1][s] = d1; sc[2][s] = d2; sc[3][s] = d3;
                }
            }
        }
    }
    if (lane == 0) {
        wred[w][0] = wmax[0]; wred[w][1] = wmax[1];
        wred[w][2] = wmax[2]; wred[w][3] = wmax[3];
    }
    __syncthreads();
    if (tid < 4) {
        float m = wred[0][tid];
#pragma unroll
        for (int i = 1; i < 8; i++) m = fmaxf(m, wred[i][tid]);
        gm[tid] = m;
    }
    __syncthreads();

    // ---- phase 2: softmax (exp in place, fixed-order sum reduction) -------
    float lsum[4] = {0.f, 0.f, 0.f, 0.f};
#pragma unroll
    for (int h = 0; h < 4; h++) {
        const float m = gm[h];
        for (int s = tid; s < S; s += 256) {
            const float e = __expf(sc[h][s] - m);
            sc[h][s] = e;
            lsum[h] += e;
        }
    }
#pragma unroll
    for (int h = 0; h < 4; h++) {
        float v = lsum[h];
#pragma unroll
        for (int off = 16; off; off >>= 1)
            v += __shfl_xor_sync(0xffffffffu, v, off);
        if (lane == 0) wred[w][h] = v;
    }
    __syncthreads();
    if (tid < 4) {
        float v = 0.f;
#pragma unroll
        for (int i = 0; i < 8; i++) v += wred[i][tid];
        ginv[tid] = 1.f / v;
    }
    __syncthreads();

    // ---- phase 3: P @ V ----------------------------------------------------
    const float* vbase = v_cache + (size_t)(b * NKV + kv) * MAXSEQ * HDIM;
    const float* vnew  = g_v + (b * NKV + kv) * HDIM;
    float acc[4][4];
#pragma unroll
    for (int h = 0; h < 4; h++)
#pragma unroll
        for (int j = 0; j < 4; j++) acc[h][j] = 0.f;

    for (int s0 = w * 4; s0 < S; s0 += 32) {
        float4 r[4];
#pragma unroll
        for (int u = 0; u < 4; u++) {
            const int s = s0 + u;
            if (s < S) {
                const float* row = (s == pos) ? vnew
                                              : (vbase + (size_t)s * HDIM);
                r[u] = *(const float4*)(row + lane * 4);
            }
        }
#pragma unroll
        for (int u = 0; u < 4; u++) {
            const int s = s0 + u;
            if (s < S) {
                const float p0 = sc[0][s], p1 = sc[1][s];
                const float p2 = sc[2][s], p3 = sc[3][s];
                acc[0][0] = fmaf(p0, r[u].x, acc[0][0]);
                acc[0][1] = fmaf(p0, r[u].y, acc[0][1]);
                acc[0][2] = fmaf(p0, r[u].z, acc[0][2]);
                acc[0][3] = fmaf(p0, r[u].w, acc[0][3]);
                acc[1][0] = fmaf(p1, r[u].x, acc[1][0]);
                acc[1][1] = fmaf(p1, r[u].y, acc[1][1]);
                acc[1][2] = fmaf(p1, r[u].z, acc[1][2]);
                acc[1][3] = fmaf(p1, r[u].w, acc[1][3]);
                acc[2][0] = fmaf(p2, r[u].x, acc[2][0]);
                acc[2][1] = fmaf(p2, r[u].y, acc[2][1]);
                acc[2][2] = fmaf(p2, r[u].z, acc[2][2]);
                acc[2][3] = fmaf(p2, r[u].w, acc[2][3]);
                acc[3][0] = fmaf(p3, r[u].x, acc[3][0]);
                acc[3][1] = fmaf(p3, r[u].y, acc[3][1]);
                acc[3][2] = fmaf(p3, r[u].z, acc[3][2]);
                acc[3][3] = fmaf(p3, r[u].w, acc[3][3]);
            }
        }
    }
#pragma unroll
    for (int h = 0; h < 4; h++)
#pragma unroll
        for (int j = 0; j < 4; j++)
            wout[w][h][lane * 4 + j] = acc[h][j];
    __syncthreads();

    for (int i = tid; i < 4 * HDIM; i += 256) {
        const int h = i >> 7, d = i & 127;
        float v = 0.f;
#pragma unroll
        for (int ww = 0; ww < 8; ww++) v += wout[ww][h][d];
        g_attn[b * HIDDEN + (kv * 4 + h) * HDIM + d] = v * ginv[h];
    }
}

// Final K-split reduce for the output projection. grid (16, 32) x 128.
__global__ __launch_bounds__(128) void reduce_out(float* __restrict__ out)
{
    const int tile = blockIdx.x, b = blockIdx.y, d = threadIdx.x;
    const size_t base = (size_t)tile * 32768 + (size_t)b * 128 + d;
    float v = 0.f;
#pragma unroll
    for (int s = 0; s < 8; s++) v += g_part[base + (size_t)s * 4096];
    out[b * HIDDEN + tile * 128 + d] = v;
}

// ---------------------------------------------------------------------------
extern "C" void kernel_launch(void* const* d_in, const int* in_sizes, int n_in,
                              void* d_out, int out_size)
{
    const float* x        = (const float*)d_in[0];
    const float* position = (const float*)d_in[1];
    // d_in[2] = mask (unused: equivalent to the pos bound)
    const float* k_cache  = (const float*)d_in[3];
    const float* v_cache  = (const float*)d_in[4];
    // d_in[5] = onehot (unused: equivalent to s==pos row swap)
    const float* wq       = (const float*)d_in[6];
    const float* wk       = (const float*)d_in[7];
    const float* wv       = (const float*)d_in[8];
    const float* wo       = (const float*)d_in[9];
    const float* qnw      = (const float*)d_in[10];
    const float* knw      = (const float*)d_in[11];
    float* out            = (float*)d_out;

    gemm_qkv<<<dim3(24, 8), 256>>>(x, wq, wk, wv);
    reduce_norm_rope<<<dim3(24, 32), 128>>>(position, qnw, knw);
    attn_kernel<<<dim3(4, 32), 256>>>(k_cache, v_cache, position);
    gemm_o<<<dim3(16, 8), 256>>>(wo);
    reduce_out<<<dim3(16, 32), 128>>>(out);
}

// round 2
// speedup vs baseline: 1.9064x; 1.9064x over previous
#include <cuda_runtime.h>
#include <cstdint>
#include <math.h>

#define NHEADS   16
#define NKV      4
#define HDIM     128
#define HIDDEN   2048
#define MAXSEQ   1024
#define EPSV     1e-6f
#define QSCALE   0.088388347648318447f   /* 1/sqrt(128) */
#define NSLICE   16                      /* K-split for GEMMs */
#define KSLICE   (HIDDEN / NSLICE)       /* 128 */
#define KC       32                      /* smem chunk */
#define NSPLIT   4                       /* attention seq split */

typedef unsigned long long ull;

// ---------------- scratch ---------------------------------------------------
__device__ __align__(16) float g_part[24 * NSLICE * 32 * 128]; // GEMM partials
__device__ __align__(16) float g_q[32 * NHEADS * HDIM];
__device__ __align__(16) float g_k[32 * NKV * HDIM];
__device__ __align__(16) float g_v[32 * NKV * HDIM];
__device__ __align__(16) float g_attn[32 * HIDDEN];
__device__ __align__(16) float g_pa[32 * NKV * NSPLIT * 4 * HDIM]; // attn partial acc
__device__ float g_pm[32 * NKV * NSPLIT * 4];                      // partial max
__device__ float g_ps[32 * NKV * NSPLIT * 4];                      // partial sum

// packed dual-fp32 FMA (FFMA2) — PTX-only on sm_103a
__device__ __forceinline__ ull fma2(ull a, ull b, ull c) {
    ull d;
    asm("fma.rn.f32x2 %0, %1, %2, %3;" : "=l"(d) : "l"(a), "l"(b), "l"(c));
    return d;
}

// ---------------------------------------------------------------------------
// GEMM block: out[32 b][128 f] partial over one 128-wide K slice.
// 128 threads; per-thread 4(m) x 8(n, as 4 f32x2 pairs at n = tn*2 + p*32).
// ---------------------------------------------------------------------------
__device__ __forceinline__ void gemm_block(const float* __restrict__ X,
                                           const float* __restrict__ Wt,
                                           float* __restrict__ outp,
                                           int kstart)
{
    __shared__ float  w_s[KC][130];      // [k][f], pad 130: even + conflict-ok
    __shared__ float2 x_s[KC][32];       // [k][b], value duplicated in .x/.y

    const int tid = threadIdx.x;
    const int tn2 = (tid & 15) * 2;      // n base (pairs at +0,+32,+64,+96)
    const int tm4 = (tid >> 4) * 2 * 2;  // m base (4 batches)

    ull acc[4][4];
#pragma unroll
    for (int i = 0; i < 4; i++)
#pragma unroll
        for (int p = 0; p < 4; p++) acc[i][p] = 0ULL;

    const int kq = (tid & 7) * 4;        // W loader: k offset
    const int f0 = tid >> 3;             // W loader: feature base 0..15

    for (int kc = 0; kc < KSLICE; kc += KC) {
        const int kb = kstart + kc;
        // --- W chunk: 128 f x 32 k, coalesced LDG, transposed store -------
#pragma unroll
        for (int r = 0; r < 8; r++) {
            const int f = f0 + r * 16;
            float4 v = *(const float4*)(Wt + (size_t)f * HIDDEN + kb + kq);
            w_s[kq + 0][f] = v.x;
            w_s[kq + 1][f] = v.y;
            w_s[kq + 2][f] = v.z;
            w_s[kq + 3][f] = v.w;
        }
        // --- X chunk: 32 b x 32 k, duplicated float2 (tiny, L2-hot) -------
        if (tid < 32) {
            const int b = tid;
#pragma unroll
            for (int q = 0; q < 8; q++) {
                float4 v = *(const float4*)(X + (size_t)b * HIDDEN + kb + q * 4);
                x_s[q * 4 + 0][b] = make_float2(v.x, v.x);
                x_s[q * 4 + 1][b] = make_float2(v.y, v.y);
                x_s[q * 4 + 2][b] = make_float2(v.z, v.z);
                x_s[q * 4 + 3][b] = make_float2(v.w, v.w);
            }
        }
        __syncthreads();
#pragma unroll
        for (int k = 0; k < KC; k++) {
            const ulonglong2 xa = *(const ulonglong2*)&x_s[k][tm4];     // b0,b1
            const ulonglong2 xb = *(const ulonglong2*)&x_s[k][tm4 + 2]; // b2,b3
            const ull w0 = *(const ull*)&w_s[k][tn2];
            const ull w1 = *(const ull*)&w_s[k][tn2 + 32];
            const ull w2 = *(const ull*)&w_s[k][tn2 + 64];
            const ull w3 = *(const ull*)&w_s[k][tn2 + 96];
            acc[0][0] = fma2(w0, xa.x, acc[0][0]);
            acc[0][1] = fma2(w1, xa.x, acc[0][1]);
            acc[0][2] = fma2(w2, xa.x, acc[0][2]);
            acc[0][3] = fma2(w3, xa.x, acc[0][3]);
            acc[1][0] = fma2(w0, xa.y, acc[1][0]);
            acc[1][1] = fma2(w1, xa.y, acc[1][1]);
            acc[1][2] = fma2(w2, xa.y, acc[1][2]);
            acc[1][3] = fma2(w3, xa.y, acc[1][3]);
            acc[2][0] = fma2(w0, xb.x, acc[2][0]);
            acc[2][1] = fma2(w1, xb.x, acc[2][1]);
            acc[2][2] = fma2(w2, xb.x, acc[2][2]);
            acc[2][3] = fma2(w3, xb.x, acc[2][3]);
            acc[3][0] = fma2(w0, xb.y, acc[3][0]);
            acc[3][1] = fma2(w1, xb.y, acc[3][1]);
            acc[3][2] = fma2(w2, xb.y, acc[3][2]);
            acc[3][3] = fma2(w3, xb.y, acc[3][3]);
        }
        __syncthreads();
    }
#pragma unroll
    for (int i = 0; i < 4; i++)
#pragma unroll
        for (int p = 0; p < 4; p++)
            *(ull*)(outp + (size_t)(tm4 + i) * 128 + tn2 + p * 32) = acc[i][p];
}

// tiles 0..15 = wq (16 heads), 16..19 = wk, 20..23 = wv. grid (24, NSLICE)
__global__ __launch_bounds__(128) void gemm_qkv(const float* __restrict__ x,
                                                const float* __restrict__ wq,
                                                const float* __restrict__ wk,
                                                const float* __restrict__ wv)
{
    const int tile = blockIdx.x, slice = blockIdx.y;
    const float* Wt;
    if (tile < 16)      Wt = wq + (size_t)tile * 128 * HIDDEN;
    else if (tile < 20) Wt = wk + (size_t)(tile - 16) * 128 * HIDDEN;
    else                Wt = wv + (size_t)(tile - 20) * 128 * HIDDEN;
    gemm_block(x, Wt, g_part + (size_t)(tile * NSLICE + slice) * 4096,
               slice * KSLICE);
}

// grid (16, NSLICE)
__global__ __launch_bounds__(128) void gemm_o(const float* __restrict__ wo)
{
    const int tile = blockIdx.x, slice = blockIdx.y;
    gemm_block(g_attn, wo + (size_t)tile * 128 * HIDDEN,
               g_part + (size_t)(tile * NSLICE + slice) * 4096, slice * KSLICE);
}

// ---------------------------------------------------------------------------
// Reduce K-split partials, then RMSnorm + RoPE for q/k heads.
// grid (24, 32) x 128
// ---------------------------------------------------------------------------
__global__ __launch_bounds__(128) void reduce_norm_rope(
    const float* __restrict__ position,
    const float* __restrict__ qnw, const float* __restrict__ knw)
{
    const int head = blockIdx.x, b = blockIdx.y, d = threadIdx.x;
    const size_t base = (size_t)head * NSLICE * 4096 + (size_t)b * 128 + d;
    float v = 0.f;
#pragma unroll
    for (int s = 0; s < NSLICE; s++) v += g_part[base + (size_t)s * 4096];

    if (head >= 20) {
        g_v[(b * NKV + head - 20) * HDIM + d] = v;
        return;
    }

    __shared__ float red[4];
    __shared__ float sv[128];

    float sq = v * v;
#pragma unroll
    for (int off = 16; off; off >>= 1)
        sq += __shfl_xor_sync(0xffffffffu, sq, off);
    if ((d & 31) == 0) red[d >> 5] = sq;
    __syncthreads();
    const float ssq  = red[0] + red[1] + red[2] + red[3];
    const float norm = rsqrtf(ssq * (1.f / 128.f) + EPSV);
    const float nv   = v * norm * ((head < 16) ? qnw[d] : knw[d]);
    sv[d] = nv;
    __syncthreads();

    const float pos = position[0];
    const int   j   = d & 63;
    const float fr  = pos * exp2f((float)j * (-19.93156856932417f / 64.f));
    float c, s;
    sincosf(fr, &s, &c);
    const float other = (d < 64) ? sv[d + 64] : sv[d - 64];
    const float out   = (d < 64) ? (nv * c - other * s)
                                 : (nv * c + other * s);
    if (head < 16) g_q[(b * NHEADS + head) * HDIM + d] = out * QSCALE;
    else           g_k[(b * NKV + head - 16) * HDIM + d] = out;
}

// ---------------------------------------------------------------------------
// Attention partial: block (kv, b, split c). 4 q-heads share K/V reads.
// Writes un-normalized partial (max, expsum, acc) for split c.
// ---------------------------------------------------------------------------
__global__ __launch_bounds__(256) void attn_part(
    const float* __restrict__ k_cache, const float* __restrict__ v_cache,
    const float* __restrict__ position)
{
    const int kv = blockIdx.x, b = blockIdx.y, c = blockIdx.z;
    const int tid = threadIdx.x;
    const int lane = tid & 31, w = tid >> 5;
    const int pos = (int)position[0];
    const int S   = pos + 1;
    const int LEN = (S + NSPLIT - 1) / NSPLIT;       // <= 256
    const int lo  = c * LEN;
    const int hi  = min(S, lo + LEN);

    __shared__ float q_s[4][HDIM];
    __shared__ float sc[4][(MAXSEQ + NSPLIT - 1) / NSPLIT + 4];
    __shared__ float wred[8][4];
    __shared__ float gm[4];
    __shared__ float wout[8][4][HDIM];

    for (int i = tid; i < 4 * HDIM; i += 256) {
        const int h = i >> 7, d = i & 127;
        q_s[h][d] = g_q[(b * NHEADS + kv * 4 + h) * HDIM + d];
    }
    __syncthreads();

    float qr[4][4];
#pragma unroll
    for (int h = 0; h < 4; h++)
#pragma unroll
        for (int j = 0; j < 4; j++) qr[h][j] = q_s[h][lane * 4 + j];

    const float* kbase = k_cache + (size_t)(b * NKV + kv) * MAXSEQ * HDIM;
    const float* knew  = g_k + (b * NKV + kv) * HDIM;

    float wmax[4] = {-1e30f, -1e30f, -1e30f, -1e30f};

    // ---- phase 1: scores --------------------------------------------------
    for (int s0 = lo + w * 4; s0 < hi; s0 += 32) {
        float4 r[4];
#pragma unroll
        for (int u = 0; u < 4; u++) {
            const int s = s0 + u;
            if (s < hi) {
                const float* row = (s == pos) ? knew
                                              : (kbase + (size_t)s * HDIM);
                r[u] = *(const float4*)(row + lane * 4);
            }
        }
#pragma unroll
        for (int u = 0; u < 4; u++) {
            const int s = s0 + u;
            if (s < hi) {
                float d0 = fmaf(r[u].x, qr[0][0], fmaf(r[u].y, qr[0][1],
                           fmaf(r[u].z, qr[0][2], r[u].w * qr[0][3])));
                float d1 = fmaf(r[u].x, qr[1][0], fmaf(r[u].y, qr[1][1],
                           fmaf(r[u].z, qr[1][2], r[u].w * qr[1][3])));
                float d2 = fmaf(r[u].x, qr[2][0], fmaf(r[u].y, qr[2][1],
                           fmaf(r[u].z, qr[2][2], r[u].w * qr[2][3])));
                float d3 = fmaf(r[u].x, qr[3][0], fmaf(r[u].y, qr[3][1],
                           fmaf(r[u].z, qr[3][2], r[u].w * qr[3][3])));
#pragma unroll
                for (int off = 16; off; off >>= 1) {
                    d0 += __shfl_xor_sync(0xffffffffu, d0, off);
                    d1 += __shfl_xor_sync(0xffffffffu, d1, off);
                    d2 += __shfl_xor_sync(0xffffffffu, d2, off);
                    d3 += __shfl_xor_sync(0xffffffffu, d3, off);
                }
                wmax[0] = fmaxf(wmax[0], d0);
                wmax[1] = fmaxf(wmax[1], d1);
                wmax[2] = fmaxf(wmax[2], d2);
                wmax[3] = fmaxf(wmax[3], d3);
                if (lane == 0) {
                    sc[0][s - lo] = d0; sc[1][s - lo] = d1;
                    sc[2][s - lo] = d2; sc[3][s - lo] = d3;
                }
            }
        }
    }
    if (lane == 0) {
        wred[w][0] = wmax[0]; wred[w][1] = wmax[1];
        wred[w][2] = wmax[2]; wred[w][3] = wmax[3];
    }
    __syncthreads();
    if (tid < 4) {
        float m = wred[0][tid];
#pragma unroll
        for (int i = 1; i < 8; i++) m = fmaxf(m, wred[i][tid]);
        gm[tid] = m;
    }
    __syncthreads();

    // ---- phase 2: exp + partial sum ---------------------------------------
    float lsum[4] = {0.f, 0.f, 0.f, 0.f};
#pragma unroll
    for (int h = 0; h < 4; h++) {
        const float m = gm[h];
        for (int s = lo + tid; s < hi; s += 256) {
            const float e = __expf(sc[h][s - lo] - m);
            sc[h][s - lo] = e;
            lsum[h] += e;
        }
    }
#pragma unroll
    for (int h = 0; h < 4; h++) {
        float v = lsum[h];
#pragma unroll
        for (int off = 16; off; off >>= 1)
            v += __shfl_xor_sync(0xffffffffu, v, off);
        if (lane == 0) wred[w][h] = v;
    }
    __syncthreads();
    if (tid < 4) {
        float v = 0.f;
#pragma unroll
        for (int i = 0; i < 8; i++) v += wred[i][tid];
        const int pbase = ((b * NKV + kv) * NSPLIT + c) * 4 + tid;
        g_ps[pbase] = v;
        g_pm[pbase] = gm[tid];
    }
    __syncthreads();

    // ---- phase 3: P @ V ----------------------------------------------------
    const float* vbase = v_cache + (size_t)(b * NKV + kv) * MAXSEQ * HDIM;
    const float* vnew  = g_v + (b * NKV + kv) * HDIM;
    float acc[4][4];
#pragma unroll
    for (int h = 0; h < 4; h++)
#pragma unroll
        for (int j = 0; j < 4; j++) acc[h][j] = 0.f;

    for (int s0 = lo + w * 4; s0 < hi; s0 += 32) {
        float4 r[4];
#pragma unroll
        for (int u = 0; u < 4; u++) {
            const int s = s0 + u;
            if (s < hi) {
                const float* row = (s == pos) ? vnew
                                              : (vbase + (size_t)s * HDIM);
                r[u] = *(const float4*)(row + lane * 4);
            }
        }
#pragma unroll
        for (int u = 0; u < 4; u++) {
            const int s = s0 + u;
            if (s < hi) {
                const float p0 = sc[0][s - lo], p1 = sc[1][s - lo];
                const float p2 = sc[2][s - lo], p3 = sc[3][s - lo];
                acc[0][0] = fmaf(p0, r[u].x, acc[0][0]);
                acc[0][1] = fmaf(p0, r[u].y, acc[0][1]);
                acc[0][2] = fmaf(p0, r[u].z, acc[0][2]);
                acc[0][3] = fmaf(p0, r[u].w, acc[0][3]);
                acc[1][0] = fmaf(p1, r[u].x, acc[1][0]);
                acc[1][1] = fmaf(p1, r[u].y, acc[1][1]);
                acc[1][2] = fmaf(p1, r[u].z, acc[1][2]);
                acc[1][3] = fmaf(p1, r[u].w, acc[1][3]);
                acc[2][0] = fmaf(p2, r[u].x, acc[2][0]);
                acc[2][1] = fmaf(p2, r[u].y, acc[2][1]);
                acc[2][2] = fmaf(p2, r[u].z, acc[2][2]);
                acc[2][3] = fmaf(p2, r[u].w, acc[2][3]);
                acc[3][0] = fmaf(p3, r[u].x, acc[3][0]);
                acc[3][1] = fmaf(p3, r[u].y, acc[3][1]);
                acc[3][2] = fmaf(p3, r[u].z, acc[3][2]);
                acc[3][3] = fmaf(p3, r[u].w, acc[3][3]);
            }
        }
    }
#pragma unroll
    for (int h = 0; h < 4; h++)
#pragma unroll
        for (int j = 0; j < 4; j++)
            wout[w][h][lane * 4 + j] = acc[h][j];
    __syncthreads();

    for (int i = tid; i < 4 * HDIM; i += 256) {
        const int h = i >> 7, d = i & 127;
        float v = 0.f;
#pragma unroll
        for (int ww = 0; ww < 8; ww++) v += wout[ww][h][d];
        g_pa[(((size_t)(b * NKV + kv) * NSPLIT + c) * 4 + h) * HDIM + d] = v;
    }
}

// Combine splits: grid (4, 32) x 128
__global__ __launch_bounds__(128) void attn_combine()
{
    const int kv = blockIdx.x, b = blockIdx.y, d = threadIdx.x;
#pragma unroll
    for (int h = 0; h < 4; h++) {
        const int sb = ((b * NKV + kv) * NSPLIT) * 4 + h;
        float m = -1e30f;
#pragma unroll
        for (int c = 0; c < NSPLIT; c++) m = fmaxf(m, g_pm[sb + c * 4]);
        float den = 0.f, val = 0.f;
#pragma unroll
        for (int c = 0; c < NSPLIT; c++) {
            const float wc = __expf(g_pm[sb + c * 4] - m);
            den += g_ps[sb + c * 4] * wc;
            val = fmaf(g_pa[(size_t)(sb + c * 4) * HDIM + d], wc, val);
        }
        g_attn[b * HIDDEN + (kv * 4 + h) * HDIM + d] = val / den;
    }
}

// Final K-split reduce for output projection. grid (16, 32) x 128
__global__ __launch_bounds__(128) void reduce_out(float* __restrict__ out)
{
    const int tile = blockIdx.x, b = blockIdx.y, d = threadIdx.x;
    const size_t base = (size_t)tile * NSLICE * 4096 + (size_t)b * 128 + d;
    float v = 0.f;
#pragma unroll
    for (int s = 0; s < NSLICE; s++) v += g_part[base + (size_t)s * 4096];
    out[b * HIDDEN + tile * 128 + d] = v;
}

// ---------------------------------------------------------------------------
extern "C" void kernel_launch(void* const* d_in, const int* in_sizes, int n_in,
                              void* d_out, int out_size)
{
    const float* x        = (const float*)d_in[0];
    const float* position = (const float*)d_in[1];
    const float* k_cache  = (const float*)d_in[3];
    const float* v_cache  = (const float*)d_in[4];
    const float* wq       = (const float*)d_in[6];
    const float* wk       = (const float*)d_in[7];
    const float* wv       = (const float*)d_in[8];
    const float* wo       = (const float*)d_in[9];
    const float* qnw      = (const float*)d_in[10];
    const float* knw      = (const float*)d_in[11];
    float* out            = (float*)d_out;

    gemm_qkv<<<dim3(24, NSLICE), 128>>>(x, wq, wk, wv);
    reduce_norm_rope<<<dim3(24, 32), 128>>>(position, qnw, knw);
    attn_part<<<dim3(NKV, 32, NSPLIT), 256>>>(k_cache, v_cache, position);
    attn_combine<<<dim3(NKV, 32), 128>>>();
    gemm_o<<<dim3(16, NSLICE), 128>>>(wo);
    reduce_out<<<dim3(16, 32), 128>>>(out);
}